// round 2
// baseline (speedup 1.0000x reference)
#include <cuda_runtime.h>

// CIN (xDeepFM) fused 3-layer kernel — round 2.
// B=4096, F0=39, D=16, H=128 per layer, Fi = {39,128,128}.
// Z_l[b,h,d] = b_l[h] + sum_j X0[b,j,d] * (sum_k W_l[h, j*Fi+k] * Xi[b,k,d])
// out[b, l*128+h] = sum_d Z_l[b,h,d]
//
// Layout: 256 threads = 2 batches x (2 d-groups x 64 hh). Each thread computes
// 2 h-values (hh, hh+64) x 8 d-values (4 packed f32x2). Weights are stored
// transposed AND pre-duplicated as packed f32x2 so the inner loop is pure
// LDG.64 + LDS.128 + FFMA2.

#define THREADS 256
#define NB      2       // batches per block
#define HD      128
#define F0C     39
#define DD      16
#define DP      4       // 4 packed f32x2 pairs = 8 d values per thread
#define ROWS    20      // smem row stride in floats (80B)

typedef unsigned long long u64;

// Transposed + duplicated weights: WT[c*128 + h] = pack(W[h*cin+c], W[h*cin+c])
__device__ u64 WT0g[39 * 39 * 128];
__device__ u64 WT1g[39 * 128 * 128];
__device__ u64 WT2g[39 * 128 * 128];

__device__ __forceinline__ u64 pk1(float w) {
    u64 r; asm("mov.b64 %0, {%1, %1};" : "=l"(r) : "f"(w)); return r;
}
__device__ __forceinline__ u64 fma2(u64 a, u64 b, u64 c) {
    u64 r; asm("fma.rn.f32x2 %0, %1, %2, %3;" : "=l"(r) : "l"(a), "l"(b), "l"(c));
    return r;
}

// -------------------- W transpose+pack: [H, cin] -> [cin, H] (dup f32x2) ----
__global__ void transpose_w(const float* __restrict__ W, u64* __restrict__ WT, int cin) {
    __shared__ float t[32][33];
    int cb = blockIdx.x * 32, hb = blockIdx.y * 32;
    int x = threadIdx.x, y = threadIdx.y;  // (32, 8)
    #pragma unroll
    for (int i = y; i < 32; i += 8) {
        int c = cb + x;
        if (c < cin) t[i][x] = W[(hb + i) * cin + c];
    }
    __syncthreads();
    #pragma unroll
    for (int i = y; i < 32; i += 8) {
        int c = cb + i;
        if (c < cin) WT[c * 128 + hb + x] = pk1(t[x][i]);
    }
}

// -------------------- one CIN layer: 2 h-values x 8 d-values ---------------
// xi, x0 point at this thread's 32-byte d-chunk of the row (smem).
template <int FI>
__device__ __forceinline__ void cin_layer(
    const u64* __restrict__ WT,      // [F0C*FI][128] packed weights (L2-resident)
    const float* __restrict__ bias,  // [128]
    const float* xi,
    const float* x0,
    int hh,
    u64* acc0, u64* acc1)
{
    u64 bb0 = pk1(__ldg(bias + hh));
    u64 bb1 = pk1(__ldg(bias + hh + 64));
    #pragma unroll
    for (int p = 0; p < DP; p++) { acc0[p] = bb0; acc1[p] = bb1; }

    const u64* wp = WT + hh;
    for (int j = 0; j < F0C; j++) {
        u64 s0[DP], s1[DP];
        #pragma unroll
        for (int p = 0; p < DP; p++) { s0[p] = 0ull; s1[p] = 0ull; }

        const float* xr = xi;
        #pragma unroll 4
        for (int k = 0; k < FI; k++) {
            u64 w0 = __ldg(wp);          // packed (w,w): coalesced 256B/warp
            u64 w1 = __ldg(wp + 64);
            wp += 128;
            ulonglong2 a = *(const ulonglong2*)xr;          // 8 d-values
            ulonglong2 b = *(const ulonglong2*)(xr + 4);
            xr += ROWS;
            u64 xv[DP] = { a.x, a.y, b.x, b.y };
            #pragma unroll
            for (int p = 0; p < DP; p++) {
                s0[p] = fma2(w0, xv[p], s0[p]);
                s1[p] = fma2(w1, xv[p], s1[p]);
            }
        }
        // acc += X0[j, dchunk] * s
        ulonglong2 a = *(const ulonglong2*)(x0 + j * ROWS);
        ulonglong2 b = *(const ulonglong2*)(x0 + j * ROWS + 4);
        u64 xv[DP] = { a.x, a.y, b.x, b.y };
        #pragma unroll
        for (int p = 0; p < DP; p++) {
            acc0[p] = fma2(xv[p], s0[p], acc0[p]);
            acc1[p] = fma2(xv[p], s1[p], acc1[p]);
        }
    }
}

__device__ __forceinline__ void store_z(float* dst, const u64* acc) {
    ulonglong2* d2 = (ulonglong2*)dst;
    d2[0] = make_ulonglong2(acc[0], acc[1]);
    d2[1] = make_ulonglong2(acc[2], acc[3]);
}

// -------------------- fused main kernel ------------------------------------
__global__ __launch_bounds__(THREADS, 4)
void cin_main(const float* __restrict__ x,      // [B, 39, 16]
              const float* __restrict__ bias0,
              const float* __restrict__ bias1,
              const float* __restrict__ bias2,
              float* __restrict__ out)          // [B, 384]
{
    __shared__ __align__(16) float x0s[NB][F0C * ROWS];
    __shared__ __align__(16) float xis[NB][HD * ROWS];

    int tid = threadIdx.x;
    int bl  = tid >> 7;          // local batch 0..1 (warp-uniform)
    int dg  = (tid >> 6) & 1;    // d-group 0..1 (warp-uniform)
    int hh  = tid & 63;          // handles h = hh and hh+64
    int bbase = blockIdx.x * NB;

    // stage X0 (coalesced)
    for (int i = tid; i < NB * F0C * DD; i += THREADS) {
        int bb = i / (F0C * DD);
        int r  = i - bb * (F0C * DD);
        x0s[bb][(r >> 4) * ROWS + (r & 15)] = x[(bbase + bb) * (F0C * DD) + r];
    }
    __syncthreads();

    const float* x0c = &x0s[bl][0] + dg * 8;   // this thread's 8-d chunk
    float*       xib = &xis[bl][0];
    const float* xic = xib + dg * 8;
    float*       z0  = xib + hh * ROWS + dg * 8;
    float*       z1  = xib + (hh + 64) * ROWS + dg * 8;

    // rowsum mapping: thread t sums one full Z row (16 floats)
    int rb = tid >> 7;           // batch of the row this thread reduces
    int rh = tid & 127;          // h of the row
    const float4* rrow = (const float4*)(&xis[rb][0] + rh * ROWS);
    float* orow_r = out + (size_t)(bbase + rb) * 384 + rh;

    u64 acc0[DP], acc1[DP];

    // ---- layer 0 (Xi = X0, Fi = 39) ----
    cin_layer<F0C>(WT0g, bias0, x0c, x0c, hh, acc0, acc1);
    store_z(z0, acc0);
    store_z(z1, acc1);
    __syncthreads();
    {
        float4 a = rrow[0], b = rrow[1], c = rrow[2], d = rrow[3];
        orow_r[0] = (a.x+a.y+a.z+a.w) + (b.x+b.y+b.z+b.w)
                  + (c.x+c.y+c.z+c.w) + (d.x+d.y+d.z+d.w);
    }

    // ---- layer 1 (Fi = 128), in-place Xi update ----
    cin_layer<HD>(WT1g, bias1, xic, x0c, hh, acc0, acc1);
    __syncthreads();                 // all reads of xis done before overwrite
    store_z(z0, acc0);
    store_z(z1, acc1);
    __syncthreads();
    {
        float4 a = rrow[0], b = rrow[1], c = rrow[2], d = rrow[3];
        orow_r[128] = (a.x+a.y+a.z+a.w) + (b.x+b.y+b.z+b.w)
                    + (c.x+c.y+c.z+c.w) + (d.x+d.y+d.z+d.w);
    }

    // ---- layer 2 (Fi = 128) ----
    cin_layer<HD>(WT2g, bias2, xic, x0c, hh, acc0, acc1);
    __syncthreads();
    store_z(z0, acc0);
    store_z(z1, acc1);
    __syncthreads();
    {
        float4 a = rrow[0], b = rrow[1], c = rrow[2], d = rrow[3];
        orow_r[256] = (a.x+a.y+a.z+a.w) + (b.x+b.y+b.z+b.w)
                    + (c.x+c.y+c.z+c.w) + (d.x+d.y+d.z+d.w);
    }
}

// -------------------- launch -----------------------------------------------
extern "C" void kernel_launch(void* const* d_in, const int* in_sizes, int n_in,
                              void* d_out, int out_size) {
    const float* x  = (const float*)d_in[0];
    const float* W0 = (const float*)d_in[1];
    const float* b0 = (const float*)d_in[2];
    const float* W1 = (const float*)d_in[3];
    const float* b1 = (const float*)d_in[4];
    const float* W2 = (const float*)d_in[5];
    const float* b2 = (const float*)d_in[6];
    float* out = (float*)d_out;

    u64 *wt0, *wt1, *wt2;
    cudaGetSymbolAddress((void**)&wt0, WT0g);
    cudaGetSymbolAddress((void**)&wt1, WT1g);
    cudaGetSymbolAddress((void**)&wt2, WT2g);

    dim3 tb(32, 8);
    transpose_w<<<dim3((1521 + 31) / 32, 4), tb>>>(W0, wt0, 1521);
    transpose_w<<<dim3((4992 + 31) / 32, 4), tb>>>(W1, wt1, 4992);
    transpose_w<<<dim3((4992 + 31) / 32, 4), tb>>>(W2, wt2, 4992);

    cin_main<<<4096 / NB, THREADS>>>(x, b0, b1, b2, out);
}

// round 4
// speedup vs baseline: 4.4290x; 4.4290x over previous
#include <cuda_runtime.h>
#include <cstdint>

// CIN (xDeepFM) via mma.sync tf32 (sm_103-legal HMMA path).
// B=4096, F0=39, D=16, H=128/layer, Fi={39,128,128}.
// Z[h,n] = sum_{j,k} W[h, j*Fi+k] * (X0[j,n]*Xi[k,n]),  n=(b,d), 128 n per CTA.

#define THREADS 256
#define NBT     8
#define XROW    136     // smem row stride (floats) for X0/Xi: conflict-free B loads

typedef unsigned long long u64;

// Pre-rounded (tf32) repacked weights
__device__ float W0pg[128 * 39 * 40];   // [h][j*40+kk], kk==39 -> 0
__device__ float W1pg[128 * 4992];
__device__ float W2pg[128 * 4992];

__device__ __forceinline__ uint32_t smem_u32(const void* p) {
    uint32_t a;
    asm("{ .reg .u64 t; cvta.to.shared.u64 t, %1; cvt.u32.u64 %0, t; }" : "=r"(a) : "l"(p));
    return a;
}
__device__ __forceinline__ float tf32r(float x) {
    uint32_t u; asm("cvt.rna.tf32.f32 %0, %1;" : "=r"(u) : "f"(x));
    return __uint_as_float(u);
}
__device__ __forceinline__ void cp16(uint32_t dst, const float* src) {
    asm volatile("cp.async.cg.shared.global [%0], [%1], 16;" :: "r"(dst), "l"(src) : "memory");
}
__device__ __forceinline__ void mma8(float c[4], const uint32_t a[4], uint32_t b0, uint32_t b1) {
    asm volatile(
        "mma.sync.aligned.m16n8k8.row.col.f32.tf32.tf32.f32 "
        "{%0,%1,%2,%3},{%4,%5,%6,%7},{%8,%9},{%0,%1,%2,%3};"
        : "+f"(c[0]), "+f"(c[1]), "+f"(c[2]), "+f"(c[3])
        : "r"(a[0]), "r"(a[1]), "r"(a[2]), "r"(a[3]), "r"(b0), "r"(b1));
}

// -------------------- weight prep ------------------------------------------
__global__ void pad_w0(const float* __restrict__ W0) {
    int i = blockIdx.x * 256 + threadIdx.x;
    if (i >= 128 * 1560) return;
    int h = i / 1560, r = i - h * 1560;
    int j = r / 40, kk = r - j * 40;
    W0pg[i] = (kk < 39) ? tf32r(W0[h * 1521 + j * 39 + kk]) : 0.f;
}
__global__ void round_w(const float* __restrict__ W, float* __restrict__ Wo) {
    int i = blockIdx.x * 256 + threadIdx.x;
    if (i < 128 * 4992) Wo[i] = tf32r(W[i]);
}

// -------------------- one layer GEMM ----------------------------------------
// CHUNK: k columns per pipeline stage; NCH: #chunks; WSTRIDE: smem row stride.
template <int CHUNK, int NCH, int WSTRIDE>
__device__ __forceinline__ void layer_mma(
    const float* __restrict__ Wg,   // [128][NCH*CHUNK]
    const float* xi,                // smem input rows
    const float* x0s,               // smem X0 rows (40, row 39 zero)
    float* wsm,                     // 3 stages of 128*WSTRIDE floats
    float acc[4][4][4],
    int tid)
{
    const int KROW   = NCH * CHUNK;
    const int KSTEPS = CHUNK / 8;
    const int SPR    = CHUNK / 4;   // 16B segs per row
    int lane = tid & 31, wid = tid >> 5;
    int grp = lane >> 2, tig = lane & 3;
    int h_base = (wid & 1) * 64, n_base = (wid >> 1) * 32;

    auto prefetch = [&](int c) {
        if (c < NCH) {
            float* dst = wsm + (c % 3) * (128 * WSTRIDE);
            const float* src = Wg + c * CHUNK;
            uint32_t du = smem_u32(dst);
            #pragma unroll
            for (int s = tid; s < 128 * SPR; s += THREADS) {
                int row = s / SPR, seg = s - row * SPR;
                cp16(du + (uint32_t)(row * WSTRIDE + seg * 4) * 4,
                     src + (size_t)row * KROW + seg * 4);
            }
        }
        asm volatile("cp.async.commit_group;" ::: "memory");
    };

    prefetch(0);
    prefetch(1);

    for (int c = 0; c < NCH; c++) {
        asm volatile("cp.async.wait_group 1;" ::: "memory");
        __syncthreads();                    // chunk c visible; stage (c+2)%3 free
        prefetch(c + 2);

        const float* ws = wsm + (c % 3) * (128 * WSTRIDE);
        int j   = (CHUNK == 40) ? c : (c >> 2);
        int kkb = (CHUNK == 40) ? 0 : ((c & 3) * 32);

        float x0v[4];
        #pragma unroll
        for (int nt = 0; nt < 4; nt++)
            x0v[nt] = x0s[j * XROW + n_base + nt * 8 + grp];

        #pragma unroll
        for (int ks = 0; ks < KSTEPS; ks++) {
            int k0 = ks * 8;
            uint32_t A[4][4];
            #pragma unroll
            for (int mt = 0; mt < 4; mt++) {
                const float* ab = ws + (h_base + mt * 16 + grp) * WSTRIDE + k0 + tig;
                A[mt][0] = __float_as_uint(ab[0]);
                A[mt][1] = __float_as_uint(ab[8 * WSTRIDE]);
                A[mt][2] = __float_as_uint(ab[4]);
                A[mt][3] = __float_as_uint(ab[8 * WSTRIDE + 4]);
            }
            int kk = kkb + k0 + tig;
            const float* xlo = xi + kk * XROW + n_base + grp;
            const float* xhi = xlo + 4 * XROW;
            #pragma unroll
            for (int nt = 0; nt < 4; nt++) {
                float p0 = x0v[nt] * xlo[nt * 8];
                float p1 = x0v[nt] * xhi[nt * 8];
                uint32_t B0, B1;
                asm("cvt.rna.tf32.f32 %0, %1;" : "=r"(B0) : "f"(p0));
                asm("cvt.rna.tf32.f32 %0, %1;" : "=r"(B1) : "f"(p1));
                #pragma unroll
                for (int mt = 0; mt < 4; mt++)
                    mma8(acc[mt][nt], A[mt], B0, B1);
            }
        }
    }
    asm volatile("cp.async.wait_group 0;" ::: "memory");
}

// -------------------- main fused kernel --------------------------------------
__global__ void __launch_bounds__(THREADS)
cin_mma(const float* __restrict__ x,
        const float* __restrict__ w0p, const float* __restrict__ w1p,
        const float* __restrict__ w2p,
        const float* __restrict__ b0, const float* __restrict__ b1,
        const float* __restrict__ b2,
        float* __restrict__ out)
{
    extern __shared__ float smf[];
    float* x0s = smf;                       // 40*136
    float* xis = smf + 40 * XROW;           // 128*136
    float* wsm = smf + (40 + 128) * XROW;   // 3 * 128*44

    int tid = threadIdx.x;
    int lane = tid & 31, wid = tid >> 5;
    int grp = lane >> 2, tig = lane & 3;
    int h_base = (wid & 1) * 64, n_base = (wid >> 1) * 32;
    int bbase = blockIdx.x * NBT;

    // stage X0: x[b, j, d] -> x0s[j][b*16+d]; zero pad row 39
    for (int i = tid; i < NBT * 624; i += THREADS) {
        int b = i / 624, r = i - b * 624;
        x0s[(r >> 4) * XROW + b * 16 + (r & 15)] = x[(size_t)(bbase + b) * 624 + r];
    }
    for (int i = tid; i < 128; i += THREADS) x0s[39 * XROW + i] = 0.f;
    __syncthreads();

    float acc[4][4][4];

    #pragma unroll 1
    for (int l = 0; l < 3; l++) {
        #pragma unroll
        for (int mt = 0; mt < 4; mt++)
            #pragma unroll
            for (int nt = 0; nt < 4; nt++)
                #pragma unroll
                for (int q = 0; q < 4; q++) acc[mt][nt][q] = 0.f;

        const float* bias;
        if (l == 0) {
            bias = b0;
            layer_mma<40, 39, 44>(w0p, x0s, x0s, wsm, acc, tid);
        } else if (l == 1) {
            bias = b1;
            layer_mma<32, 156, 36>(w1p, xis, x0s, wsm, acc, tid);
        } else {
            bias = b2;
            layer_mma<32, 156, 36>(w2p, xis, x0s, wsm, acc, tid);
        }

        __syncthreads();   // all reads of xis done before in-place overwrite

        // write Z (+bias) into xis
        #pragma unroll
        for (int mt = 0; mt < 4; mt++) {
            int h0 = h_base + mt * 16 + grp;
            float bv0 = __ldg(bias + h0), bv1 = __ldg(bias + h0 + 8);
            #pragma unroll
            for (int nt = 0; nt < 4; nt++) {
                int n = n_base + nt * 8 + 2 * tig;
                *(float2*)(xis + h0 * XROW + n) =
                    make_float2(acc[mt][nt][0] + bv0, acc[mt][nt][1] + bv0);
                *(float2*)(xis + (h0 + 8) * XROW + n) =
                    make_float2(acc[mt][nt][2] + bv1, acc[mt][nt][3] + bv1);
            }
        }
        __syncthreads();

        // d-sums -> out
        #pragma unroll
        for (int t = 0; t < 4; t++) {
            int idx = tid + THREADS * t;
            int b = idx >> 7, h = idx & 127;
            const float4* p4 = (const float4*)(xis + h * XROW + b * 16);
            float4 a = p4[0], c4 = p4[1], e = p4[2], g = p4[3];
            out[(size_t)(bbase + b) * 384 + l * 128 + h] =
                (a.x + a.y + a.z + a.w) + (c4.x + c4.y + c4.z + c4.w) +
                (e.x + e.y + e.z + e.w) + (g.x + g.y + g.z + g.w);
        }
        __syncthreads();
    }
}

// -------------------- launch -------------------------------------------------
extern "C" void kernel_launch(void* const* d_in, const int* in_sizes, int n_in,
                              void* d_out, int out_size) {
    const float* x  = (const float*)d_in[0];
    const float* W0 = (const float*)d_in[1];
    const float* b0 = (const float*)d_in[2];
    const float* W1 = (const float*)d_in[3];
    const float* b1 = (const float*)d_in[4];
    const float* W2 = (const float*)d_in[5];
    const float* b2 = (const float*)d_in[6];
    float* out = (float*)d_out;

    float *w0p, *w1p, *w2p;
    cudaGetSymbolAddress((void**)&w0p, W0pg);
    cudaGetSymbolAddress((void**)&w1p, W1pg);
    cudaGetSymbolAddress((void**)&w2p, W2pg);

    pad_w0<<<(128 * 1560 + 255) / 256, 256>>>(W0);
    round_w<<<(128 * 4992 + 255) / 256, 256>>>(W1, w1p);
    round_w<<<(128 * 4992 + 255) / 256, 256>>>(W2, w2p);

    // smem: x0s 40*136 + xis 128*136 + W stages 3*128*44  (floats)
    int smem_bytes = (40 * XROW + 128 * XROW + 3 * 128 * 44) * 4;
    cudaFuncSetAttribute(cin_mma, cudaFuncAttributeMaxDynamicSharedMemorySize, smem_bytes);
    cin_mma<<<4096 / NBT, THREADS, smem_bytes>>>(x, w0p, w1p, w2p, b0, b1, b2, out);
}